// round 1
// baseline (speedup 1.0000x reference)
#include <cuda_runtime.h>
#include <cstdint>

#define SS   2048   // seq
#define BB   2      // batch
#define EE   1024   // embed
#define HH   16     // heads
#define DD   64     // head dim
#define BH   (BB*HH)     // 32
#define TOK  (BB*SS)     // 4096

// ---------------- scratch (device globals; no allocation allowed) ----------------
__device__ float g_xt[TOK * EE];                 // x in [B,S,E] token-major (16MB)
__device__ float g_Q[BH * SS * DD];              // [B*H, S, d]
__device__ float g_K[BH * SS * DD];
__device__ float g_V[BH * SS * DD];
__device__ float g_P[(size_t)BH * SS * SS];      // attn probs [B*H, S, S] (512MB)
__device__ float g_WA[TOK * EE];                 // attn output, token-major [B,S,E]

// ---------------- kernel 0: x [S,B,E] -> xt [B,S,E] ----------------
__global__ void k_transpose(const float* __restrict__ x) {
    int idx = blockIdx.x * 256 + threadIdx.x;    // over TOK*EE
    int t = idx >> 10;                           // token (b*S+s)
    int e = idx & (EE - 1);
    int b = t >> 11;
    int s = t & (SS - 1);
    g_xt[idx] = x[((size_t)s * BB + b) * EE + e];
}

// ---------------- shared 128x128x8 fp32 GEMM core ----------------
// C[128,128] tile of A[M,K](row-major, lda) @ B[N,K]^T (row-major, ldb)
__device__ __forceinline__ void gemm_core_128(
    const float* __restrict__ A, const float* __restrict__ Bm,
    int lda, int ldb, int K, int m0, int n0, float acc[8][8])
{
    __shared__ float As[8][128];
    __shared__ float Bs[8][128];
    int tid  = threadIdx.x;            // 256 threads
    int ty   = tid >> 4;               // 0..15
    int tx   = tid & 15;               // 0..15
    int lrow = tid >> 1;               // 0..127
    int lk   = (tid & 1) << 2;         // 0 or 4

    const float* Arow = A  + (size_t)(m0 + lrow) * lda + lk;
    const float* Brow = Bm + (size_t)(n0 + lrow) * ldb + lk;

    for (int kt = 0; kt < K; kt += 8) {
        float4 a = *(const float4*)(Arow + kt);
        As[lk + 0][lrow] = a.x; As[lk + 1][lrow] = a.y;
        As[lk + 2][lrow] = a.z; As[lk + 3][lrow] = a.w;
        float4 b = *(const float4*)(Brow + kt);
        Bs[lk + 0][lrow] = b.x; Bs[lk + 1][lrow] = b.y;
        Bs[lk + 2][lrow] = b.z; Bs[lk + 3][lrow] = b.w;
        __syncthreads();
        #pragma unroll
        for (int k = 0; k < 8; k++) {
            float4 a0 = *(const float4*)&As[k][ty * 8];
            float4 a1 = *(const float4*)&As[k][ty * 8 + 4];
            float4 b0 = *(const float4*)&Bs[k][tx * 8];
            float4 b1 = *(const float4*)&Bs[k][tx * 8 + 4];
            float ra[8] = {a0.x, a0.y, a0.z, a0.w, a1.x, a1.y, a1.z, a1.w};
            float rb[8] = {b0.x, b0.y, b0.z, b0.w, b1.x, b1.y, b1.z, b1.w};
            #pragma unroll
            for (int i = 0; i < 8; i++)
                #pragma unroll
                for (int j = 0; j < 8; j++)
                    acc[i][j] += ra[i] * rb[j];
        }
        __syncthreads();
    }
}

// ---------------- kernel 1: QKV projection ----------------
// C[token, c] = xt @ qkv_w^T + qkv_b ; scatter into g_Q/g_K/g_V [B*H,S,d]
__global__ void k_qkv(const float* __restrict__ qkv_w, const float* __restrict__ qkv_b) {
    float acc[8][8] = {};
    int m0 = blockIdx.y * 128;
    int n0 = blockIdx.x * 128;
    gemm_core_128(g_xt, qkv_w, EE, EE, EE, m0, n0, acc);

    int ty = threadIdx.x >> 4, tx = threadIdx.x & 15;
    int which = n0 >> 10;                        // tile fully inside one of Q/K/V
    float* dst = (which == 0) ? g_Q : (which == 1) ? g_K : g_V;
    #pragma unroll
    for (int i = 0; i < 8; i++) {
        int row = m0 + ty * 8 + i;               // token
        int b = row >> 11, s = row & (SS - 1);
        #pragma unroll
        for (int j = 0; j < 8; j++) {
            int col = n0 + tx * 8 + j;
            int h  = (col & (EE - 1)) >> 6;
            int dd = col & (DD - 1);
            dst[(((size_t)(b * HH + h) * SS + s) * DD) + dd] = acc[i][j] + qkv_b[col];
        }
    }
}

// ---------------- kernel 2: scores = Q @ K^T / sqrt(d) ----------------
__global__ void k_scores() {
    int bh = blockIdx.z;
    const float* Aq = g_Q + (size_t)bh * SS * DD;
    const float* Bk = g_K + (size_t)bh * SS * DD;
    float acc[8][8] = {};
    int m0 = blockIdx.y * 128;
    int n0 = blockIdx.x * 128;
    gemm_core_128(Aq, Bk, DD, DD, DD, m0, n0, acc);

    int ty = threadIdx.x >> 4, tx = threadIdx.x & 15;
    float* base = g_P + (size_t)bh * SS * SS;
    #pragma unroll
    for (int i = 0; i < 8; i++) {
        float* prow = base + (size_t)(m0 + ty * 8 + i) * SS + n0 + tx * 8;
        #pragma unroll
        for (int j = 0; j < 8; j++)
            prow[j] = acc[i][j] * 0.125f;        // 1/sqrt(64)
    }
}

// ---------------- kernel 3: row softmax with masks (in place on g_P) ----------------
__global__ void k_softmax(const float* __restrict__ attn_mask,
                          const unsigned char* __restrict__ kpm) {
    int row = blockIdx.x;                        // 0 .. BH*SS-1
    int q  = row & (SS - 1);
    int bh = row >> 11;
    int b  = bh >> 4;
    float* p = g_P + (size_t)row * SS;
    int tid = threadIdx.x;

    float v[8];
    float mx = -1e30f;
    #pragma unroll
    for (int i = 0; i < 8; i++) {
        int k = tid + i * 256;
        float sc = p[k] + attn_mask[q * SS + k];
        if (kpm[b * SS + k]) sc = -1e30f;
        v[i] = sc;
        mx = fmaxf(mx, sc);
    }
    __shared__ float red[256];
    red[tid] = mx; __syncthreads();
    #pragma unroll
    for (int st = 128; st > 0; st >>= 1) {
        if (tid < st) red[tid] = fmaxf(red[tid], red[tid + st]);
        __syncthreads();
    }
    float m = red[0];
    __syncthreads();

    float sum = 0.f;
    #pragma unroll
    for (int i = 0; i < 8; i++) { v[i] = __expf(v[i] - m); sum += v[i]; }
    red[tid] = sum; __syncthreads();
    #pragma unroll
    for (int st = 128; st > 0; st >>= 1) {
        if (tid < st) red[tid] += red[tid + st];
        __syncthreads();
    }
    float inv = 1.0f / red[0];
    #pragma unroll
    for (int i = 0; i < 8; i++)
        p[tid + i * 256] = v[i] * inv;
}

// ---------------- kernel 4: attn_mean = mean over heads (deterministic) ----------------
__global__ void k_attn_mean(float* __restrict__ out_am) {
    int bq = blockIdx.x;                         // b*S + q
    int b = bq >> 11, q = bq & (SS - 1);
    const float* base = g_P + ((size_t)(b * HH) * SS + q) * SS;
    const size_t hstride = (size_t)SS * SS;
    for (int k = threadIdx.x; k < SS; k += 256) {
        float sum = 0.f;
        #pragma unroll
        for (int h = 0; h < HH; h++) sum += base[(size_t)h * hstride + k];
        out_am[(size_t)bq * SS + k] = sum * (1.0f / HH);
    }
}

// ---------------- kernel 5: O = P @ V  (M=2048, N=64, K=2048) ----------------
__global__ void k_av() {
    int bh = blockIdx.z;
    int b = bh >> 4, h = bh & 15;
    const float* A  = g_P + (size_t)bh * SS * SS;     // [S, S]
    const float* Bv = g_V + (size_t)bh * SS * DD;     // [S, 64]
    __shared__ float As[16][128];
    __shared__ float Bs[16][64];
    int tid = threadIdx.x;
    int ty = tid >> 4, tx = tid & 15;
    int m0 = blockIdx.y * 128;
    int bk = tid >> 4;               // 0..15
    int bn = (tid & 15) << 2;        // 0..60
    float acc[8][4] = {};

    for (int kt = 0; kt < SS; kt += 16) {
        #pragma unroll
        for (int i = 0; i < 2; i++) {
            int lin = tid + i * 256;
            int m   = lin >> 2;
            int k4  = (lin & 3) << 2;
            float4 a = *(const float4*)(A + (size_t)(m0 + m) * SS + kt + k4);
            As[k4 + 0][m] = a.x; As[k4 + 1][m] = a.y;
            As[k4 + 2][m] = a.z; As[k4 + 3][m] = a.w;
        }
        float4 bv = *(const float4*)(Bv + (size_t)(kt + bk) * DD + bn);
        Bs[bk][bn + 0] = bv.x; Bs[bk][bn + 1] = bv.y;
        Bs[bk][bn + 2] = bv.z; Bs[bk][bn + 3] = bv.w;
        __syncthreads();
        #pragma unroll
        for (int k = 0; k < 16; k++) {
            float4 a0 = *(const float4*)&As[k][ty * 8];
            float4 a1 = *(const float4*)&As[k][ty * 8 + 4];
            float4 b0 = *(const float4*)&Bs[k][tx * 4];
            float ra[8] = {a0.x, a0.y, a0.z, a0.w, a1.x, a1.y, a1.z, a1.w};
            float rb[4] = {b0.x, b0.y, b0.z, b0.w};
            #pragma unroll
            for (int i = 0; i < 8; i++)
                #pragma unroll
                for (int j = 0; j < 4; j++)
                    acc[i][j] += ra[i] * rb[j];
        }
        __syncthreads();
    }
    // write to token-major wa [B,S,E] with E index = h*64 + col
    #pragma unroll
    for (int i = 0; i < 8; i++) {
        int q = m0 + ty * 8 + i;
        float* dst = g_WA + (size_t)(b * SS + q) * EE + h * DD + tx * 4;
        #pragma unroll
        for (int j = 0; j < 4; j++) dst[j] = acc[i][j];
    }
}

// ---------------- kernel 6: out = wa @ out_w^T + out_b, write [S,B,E] ----------------
__global__ void k_out(const float* __restrict__ out_w, const float* __restrict__ out_b,
                      float* __restrict__ dout) {
    float acc[8][8] = {};
    int m0 = blockIdx.y * 128;
    int n0 = blockIdx.x * 128;
    gemm_core_128(g_WA, out_w, EE, EE, EE, m0, n0, acc);

    int ty = threadIdx.x >> 4, tx = threadIdx.x & 15;
    #pragma unroll
    for (int i = 0; i < 8; i++) {
        int row = m0 + ty * 8 + i;               // token
        int b = row >> 11, s = row & (SS - 1);
        float* drow = dout + ((size_t)s * BB + b) * EE + n0 + tx * 8;
        #pragma unroll
        for (int j = 0; j < 8; j++)
            drow[j] = acc[i][j] + out_b[n0 + tx * 8 + j];
    }
}

// ---------------- launch ----------------
extern "C" void kernel_launch(void* const* d_in, const int* in_sizes, int n_in,
                              void* d_out, int out_size) {
    const float*         x         = (const float*)d_in[0];
    const float*         attn_mask = (const float*)d_in[1];
    const unsigned char* kpm       = (const unsigned char*)d_in[2];
    const float*         qkv_w     = (const float*)d_in[3];
    const float*         qkv_b     = (const float*)d_in[4];
    const float*         out_w     = (const float*)d_in[5];
    const float*         out_b     = (const float*)d_in[6];

    float* out    = (float*)d_out;                       // [S,B,E]
    float* out_am = out + (size_t)SS * BB * EE;          // [B,S,S]

    k_transpose<<<(TOK * EE) / 256, 256>>>(x);
    k_qkv<<<dim3(3 * EE / 128, TOK / 128), 256>>>(qkv_w, qkv_b);
    k_scores<<<dim3(SS / 128, SS / 128, BH), 256>>>();
    k_softmax<<<BH * SS, 256>>>(attn_mask, kpm);
    k_attn_mean<<<BB * SS, 256>>>(out_am);
    k_av<<<dim3(1, SS / 128, BH), 256>>>();
    k_out<<<dim3(EE / 128, TOK / 128), 256>>>(out_w, out_b, out);
}

// round 4
// speedup vs baseline: 1.3884x; 1.3884x over previous
#include <cuda_runtime.h>
#include <cstdint>

#define SS   2048
#define BB   2
#define EE   1024
#define HH   16
#define DD   64
#define BH   (BB*HH)
#define TOK  (BB*SS)
#define NT   256

// ---------------- scratch ----------------
__device__ float g_xt[TOK * EE];                 // x token-major [B,S,E]
__device__ float g_Q[BH * SS * DD];              // [B*H, S, d]
__device__ float g_K[BH * SS * DD];
__device__ float g_V[BH * SS * DD];
__device__ float g_P[(size_t)BH * SS * SS];      // attn probs [B*H, S, S]
__device__ float g_WA[TOK * EE];                 // attn out token-major

// ---------------- mma helpers ----------------
__device__ __forceinline__ float cvt_tf32(float f) {
    uint32_t u;
    asm("cvt.rna.tf32.f32 %0, %1;" : "=r"(u) : "f"(f));
    return __uint_as_float(u);
}

__device__ __forceinline__ void mma_tf32(float c[4], const uint32_t a[4],
                                         uint32_t b0, uint32_t b1) {
    asm volatile("mma.sync.aligned.m16n8k8.row.col.f32.tf32.tf32.f32 "
                 "{%0,%1,%2,%3}, {%4,%5,%6,%7}, {%8,%9}, {%0,%1,%2,%3};"
                 : "+f"(c[0]), "+f"(c[1]), "+f"(c[2]), "+f"(c[3])
                 : "r"(a[0]), "r"(a[1]), "r"(a[2]), "r"(a[3]), "r"(b0), "r"(b1));
}

// ---------------- GEMM core ----------------
// C[128 x NTILE] tile at (m0,n0) of A[M,K] @ op(B).
// BTRANS=false: B is [N,K] row-major (B^T multiply), ldb = row stride.
// BTRANS=true : B is [K,N] row-major, ldb = row stride (transposed at staging).
// 256 threads: 8 warps as 2(m) x 4(n); warp tile 64 x (NTILE/4).
template<int NTILE, bool BTRANS>
__device__ __forceinline__ void gemm_mma(const float* __restrict__ A, int lda,
                                         const float* __restrict__ B, int ldb,
                                         int m0, int n0, int K,
                                         float acc[4][NTILE/32][4]) {
    constexpr int WN  = NTILE / 4;
    constexpr int NTN = WN / 8;
    constexpr int BF4 = NTILE / 64;          // B float4 loads per thread (2 or 1)
    __shared__ float As[128][17];
    __shared__ float Bs[NTILE][17];

    int tid = threadIdx.x, wid = tid >> 5, lane = tid & 31;
    int gid = lane >> 2, tig = lane & 3;
    int wm = (wid & 1) * 64, wn = (wid >> 1) * WN;

    float4 pa[2], pb[BF4];

    auto loadA = [&](int kt) {
        #pragma unroll
        for (int i = 0; i < 2; i++) {
            int slot = tid + i * 256;
            int r = slot >> 2, k4 = (slot & 3) << 2;
            pa[i] = *(const float4*)(A + (size_t)(m0 + r) * lda + kt + k4);
        }
    };
    auto loadB = [&](int kt) {
        #pragma unroll
        for (int i = 0; i < BF4; i++) {
            int slot = tid + i * 256;
            if (!BTRANS) {
                int r = slot >> 2, k4 = (slot & 3) << 2;
                pb[i] = *(const float4*)(B + (size_t)(n0 + r) * ldb + kt + k4);
            } else {
                int kk = slot / (NTILE / 4), n4 = (slot % (NTILE / 4)) * 4;
                pb[i] = *(const float4*)(B + (size_t)(kt + kk) * ldb + n0 + n4);
            }
        }
    };

    loadA(0); loadB(0);
    for (int kt = 0; kt < K; kt += 16) {
        __syncthreads();
        #pragma unroll
        for (int i = 0; i < 2; i++) {
            int slot = tid + i * 256;
            int r = slot >> 2, k4 = (slot & 3) << 2;
            As[r][k4 + 0] = cvt_tf32(pa[i].x);
            As[r][k4 + 1] = cvt_tf32(pa[i].y);
            As[r][k4 + 2] = cvt_tf32(pa[i].z);
            As[r][k4 + 3] = cvt_tf32(pa[i].w);
        }
        #pragma unroll
        for (int i = 0; i < BF4; i++) {
            int slot = tid + i * 256;
            if (!BTRANS) {
                int r = slot >> 2, k4 = (slot & 3) << 2;
                Bs[r][k4 + 0] = cvt_tf32(pb[i].x);
                Bs[r][k4 + 1] = cvt_tf32(pb[i].y);
                Bs[r][k4 + 2] = cvt_tf32(pb[i].z);
                Bs[r][k4 + 3] = cvt_tf32(pb[i].w);
            } else {
                int kk = slot / (NTILE / 4), n4 = (slot % (NTILE / 4)) * 4;
                Bs[n4 + 0][kk] = cvt_tf32(pb[i].x);
                Bs[n4 + 1][kk] = cvt_tf32(pb[i].y);
                Bs[n4 + 2][kk] = cvt_tf32(pb[i].z);
                Bs[n4 + 3][kk] = cvt_tf32(pb[i].w);
            }
        }
        __syncthreads();
        if (kt + 16 < K) { loadA(kt + 16); loadB(kt + 16); }
        #pragma unroll
        for (int kk = 0; kk < 16; kk += 8) {
            uint32_t af[4][4];
            #pragma unroll
            for (int mt = 0; mt < 4; mt++) {
                af[mt][0] = __float_as_uint(As[wm + mt * 16 + gid    ][kk + tig]);
                af[mt][1] = __float_as_uint(As[wm + mt * 16 + gid + 8][kk + tig]);
                af[mt][2] = __float_as_uint(As[wm + mt * 16 + gid    ][kk + tig + 4]);
                af[mt][3] = __float_as_uint(As[wm + mt * 16 + gid + 8][kk + tig + 4]);
            }
            #pragma unroll
            for (int nt = 0; nt < NTN; nt++) {
                uint32_t b0 = __float_as_uint(Bs[wn + nt * 8 + gid][kk + tig]);
                uint32_t b1 = __float_as_uint(Bs[wn + nt * 8 + gid][kk + tig + 4]);
                #pragma unroll
                for (int mt = 0; mt < 4; mt++)
                    mma_tf32(acc[mt][nt], af[mt], b0, b1);
            }
        }
    }
    __syncthreads();
}

// fragment coords: rows (gid, gid+8), cols (2*tig, 2*tig+1) within each 16x8 tile
#define EPI_SETUP() \
    int tid = threadIdx.x, wid = tid >> 5, lane = tid & 31; \
    int gid = lane >> 2, tig = lane & 3; \
    int wm = (wid & 1) * 64; (void)wm; \
    int wn = (wid >> 1) * WN; (void)wn; (void)tid;

// ---------------- kernel 0: x [S,B,E] -> xt [B,S,E] ----------------
__global__ void k_transpose(const float* __restrict__ x) {
    int idx = blockIdx.x * 256 + threadIdx.x;
    int t = idx >> 10, e = idx & (EE - 1);
    int b = t >> 11, s = t & (SS - 1);
    g_xt[idx] = x[((size_t)s * BB + b) * EE + e];
}

// ---------------- kernel 1: QKV projection ----------------
__global__ void k_qkv(const float* __restrict__ qkv_w, const float* __restrict__ qkv_b) {
    constexpr int WN = 32;
    int m0 = blockIdx.y * 128, n0 = blockIdx.x * 128;
    float acc[4][4][4] = {};
    gemm_mma<128, false>(g_xt, EE, qkv_w, EE, m0, n0, EE, acc);
    EPI_SETUP();
    int which = n0 >> 10;
    float* dst = (which == 0) ? g_Q : (which == 1) ? g_K : g_V;
    #pragma unroll
    for (int mt = 0; mt < 4; mt++) {
        #pragma unroll
        for (int nt = 0; nt < 4; nt++) {
            int col = n0 + wn + nt * 8 + 2 * tig;
            int inner = col & 1023, h = inner >> 6, dd = inner & 63;
            float b0 = qkv_b[col], b1 = qkv_b[col + 1];
            #pragma unroll
            for (int half = 0; half < 2; half++) {
                int row = m0 + wm + mt * 16 + gid + half * 8;
                int b = row >> 11, s = row & (SS - 1);
                float2 v = make_float2(acc[mt][nt][half * 2] + b0,
                                       acc[mt][nt][half * 2 + 1] + b1);
                *(float2*)&dst[((size_t)(b * HH + h) * SS + s) * DD + dd] = v;
            }
        }
    }
}

// ---------------- kernel 2: scores = QK^T/8 + masks -> g_P ----------------
__global__ void k_scores(const float* __restrict__ attn_mask,
                         const unsigned char* __restrict__ kpm) {
    constexpr int WN = 32;
    int bh = blockIdx.z, b = bh >> 4;
    int m0 = blockIdx.y * 128, n0 = blockIdx.x * 128;
    const float* Aq = g_Q + (size_t)bh * SS * DD;
    const float* Bk = g_K + (size_t)bh * SS * DD;
    float acc[4][4][4] = {};
    gemm_mma<128, false>(Aq, DD, Bk, DD, m0, n0, DD, acc);
    EPI_SETUP();
    float* pbase = g_P + (size_t)bh * SS * SS;
    #pragma unroll
    for (int mt = 0; mt < 4; mt++) {
        #pragma unroll
        for (int nt = 0; nt < 4; nt++) {
            int k = n0 + wn + nt * 8 + 2 * tig;
            float p0 = kpm[b * SS + k]     ? -1e30f : 0.0f;
            float p1 = kpm[b * SS + k + 1] ? -1e30f : 0.0f;
            #pragma unroll
            for (int half = 0; half < 2; half++) {
                int q = m0 + wm + mt * 16 + gid + half * 8;
                const float* am = attn_mask + (size_t)q * SS + k;
                float2 v = make_float2(acc[mt][nt][half * 2]     * 0.125f + am[0] + p0,
                                       acc[mt][nt][half * 2 + 1] * 0.125f + am[1] + p1);
                *(float2*)&pbase[(size_t)q * SS + k] = v;
            }
        }
    }
}

// ---------------- kernel 3: fused softmax (in place) + attn_mean ----------------
__global__ void k_softmax(float* __restrict__ out_am) {
    extern __shared__ float srows[];             // 16 x 2048
    int bq = blockIdx.x;
    int b = bq >> 11, q = bq & (SS - 1);
    int tid = threadIdx.x;
    float* pbase = g_P + ((size_t)(b * HH) * SS + q) * SS;
    const size_t hstr = (size_t)SS * SS;

    for (int h = 0; h < HH; h++) {
        float* sr = srows + h * SS;
        const float* gr = pbase + h * hstr;
        for (int i = tid; i < SS; i += 256) sr[i] = gr[i];
    }
    __syncthreads();

    int w = tid >> 5, lane = tid & 31;
    #pragma unroll
    for (int rr = 0; rr < 2; rr++) {
        int h = w * 2 + rr;
        float* sr = srows + h * SS;
        float mx = -1e30f;
        for (int i = lane; i < SS; i += 32) mx = fmaxf(mx, sr[i]);
        #pragma unroll
        for (int st = 16; st > 0; st >>= 1)
            mx = fmaxf(mx, __shfl_xor_sync(0xFFFFFFFF, mx, st));
        float sum = 0.f;
        for (int i = lane; i < SS; i += 32) {
            float e = __expf(sr[i] - mx);
            sr[i] = e; sum += e;
        }
        #pragma unroll
        for (int st = 16; st > 0; st >>= 1)
            sum += __shfl_xor_sync(0xFFFFFFFF, sum, st);
        float inv = 1.0f / sum;
        float* gr = pbase + h * hstr;
        for (int i = lane; i < SS; i += 32) {
            float p = sr[i] * inv;
            sr[i] = p; gr[i] = p;
        }
    }
    __syncthreads();

    float* am = out_am + (size_t)bq * SS;
    for (int i = tid; i < SS; i += 256) {
        float s = 0.f;
        #pragma unroll
        for (int h = 0; h < HH; h++) s += srows[h * SS + i];
        am[i] = s * (1.0f / HH);
    }
}

// ---------------- kernel 4: O = P @ V ----------------
__global__ void k_pv() {
    constexpr int WN = 16;
    int bh = blockIdx.y, b = bh >> 4, h = bh & 15;
    int m0 = blockIdx.x * 128;
    const float* A  = g_P + (size_t)bh * SS * SS;
    const float* Bv = g_V + (size_t)bh * SS * DD;   // [k][d], transposed at staging
    float acc[4][2][4] = {};
    gemm_mma<64, true>(A, SS, Bv, DD, m0, 0, SS, acc);
    EPI_SETUP();
    #pragma unroll
    for (int mt = 0; mt < 4; mt++) {
        #pragma unroll
        for (int nt = 0; nt < 2; nt++) {
            int dd = wn + nt * 8 + 2 * tig;
            #pragma unroll
            for (int half = 0; half < 2; half++) {
                int q = m0 + wm + mt * 16 + gid + half * 8;
                float2 v = make_float2(acc[mt][nt][half * 2], acc[mt][nt][half * 2 + 1]);
                *(float2*)&g_WA[(size_t)(b * SS + q) * EE + h * DD + dd] = v;
            }
        }
    }
}

// ---------------- kernel 5: out = WA @ out_w^T + out_b -> [S,B,E] ----------------
__global__ void k_out(const float* __restrict__ out_w, const float* __restrict__ out_b,
                      float* __restrict__ dout) {
    constexpr int WN = 32;
    int m0 = blockIdx.y * 128, n0 = blockIdx.x * 128;
    float acc[4][4][4] = {};
    gemm_mma<128, false>(g_WA, EE, out_w, EE, m0, n0, EE, acc);
    EPI_SETUP();
    #pragma unroll
    for (int mt = 0; mt < 4; mt++) {
        #pragma unroll
        for (int nt = 0; nt < 4; nt++) {
            int col = n0 + wn + nt * 8 + 2 * tig;
            float b0 = out_b[col], b1 = out_b[col + 1];
            #pragma unroll
            for (int half = 0; half < 2; half++) {
                int row = m0 + wm + mt * 16 + gid + half * 8;
                int b = row >> 11, s = row & (SS - 1);
                float2 v = make_float2(acc[mt][nt][half * 2] + b0,
                                       acc[mt][nt][half * 2 + 1] + b1);
                *(float2*)&dout[((size_t)s * BB + b) * EE + col] = v;
            }
        }
    }
}

// ---------------- launch ----------------
extern "C" void kernel_launch(void* const* d_in, const int* in_sizes, int n_in,
                              void* d_out, int out_size) {
    const float*         x         = (const float*)d_in[0];
    const float*         attn_mask = (const float*)d_in[1];
    const unsigned char* kpm       = (const unsigned char*)d_in[2];
    const float*         qkv_w     = (const float*)d_in[3];
    const float*         qkv_b     = (const float*)d_in[4];
    const float*         out_w     = (const float*)d_in[5];
    const float*         out_b     = (const float*)d_in[6];

    float* out    = (float*)d_out;
    float* out_am = out + (size_t)SS * BB * EE;

    const int smemSM = HH * SS * 4;              // 131072
    cudaFuncSetAttribute(k_softmax, cudaFuncAttributeMaxDynamicSharedMemorySize, smemSM);

    k_transpose<<<(TOK * EE) / 256, 256>>>(x);
    k_qkv<<<dim3(3 * EE / 128, TOK / 128), NT>>>(qkv_w, qkv_b);
    k_scores<<<dim3(SS / 128, SS / 128, BH), NT>>>(attn_mask, kpm);
    k_softmax<<<BB * SS, 256, smemSM>>>(out_am);
    k_pv<<<dim3(SS / 128, BH), NT>>>();
    k_out<<<dim3(EE / 128, TOK / 128), NT>>>(out_w, out_b, out);
}

// round 5
// speedup vs baseline: 1.8772x; 1.3521x over previous
#include <cuda_runtime.h>
#include <cstdint>

#define SS   2048
#define BB   2
#define EE   1024
#define HH   16
#define DD   64
#define BH   (BB*HH)
#define TOK  (BB*SS)
#define NT   256

// ---------------- scratch ----------------
__device__ float g_Q[BH * SS * DD];              // [B*H, S, d]
__device__ float g_K[BH * SS * DD];
__device__ float g_V[BH * SS * DD];
__device__ float g_P[(size_t)BH * SS * SS];      // attn scores/probs [B*H, S, S]
__device__ float g_WA[TOK * EE];                 // attn out token-major

// ---------------- mma helpers ----------------
__device__ __forceinline__ float cvt_tf32(float f) {
    uint32_t u;
    asm("cvt.rna.tf32.f32 %0, %1;" : "=r"(u) : "f"(f));
    return __uint_as_float(u);
}

__device__ __forceinline__ void mma_tf32(float c[4], const uint32_t a[4],
                                         uint32_t b0, uint32_t b1) {
    asm volatile("mma.sync.aligned.m16n8k8.row.col.f32.tf32.tf32.f32 "
                 "{%0,%1,%2,%3}, {%4,%5,%6,%7}, {%8,%9}, {%0,%1,%2,%3};"
                 : "+f"(c[0]), "+f"(c[1]), "+f"(c[2]), "+f"(c[3])
                 : "r"(a[0]), "r"(a[1]), "r"(a[2]), "r"(a[3]), "r"(b0), "r"(b1));
}

// ---------------- GEMM core ----------------
// C[128 x NTILE] tile at (m0,n0) of A[M,K] @ op(B).
// BTRANS=false: B is [N,K] row-major (B^T multiply). BTRANS=true: B is [K,N].
// 256 threads: 8 warps as 2(m) x 4(n); warp tile 64 x (NTILE/4).
template<int NTILE, bool BTRANS>
__device__ __forceinline__ void gemm_mma(const float* __restrict__ A, int lda,
                                         const float* __restrict__ B, int ldb,
                                         int m0, int n0, int K,
                                         float acc[4][NTILE/32][4]) {
    constexpr int WN  = NTILE / 4;
    constexpr int NTN = WN / 8;
    constexpr int BF4 = NTILE / 64;
    __shared__ float As[128][17];
    __shared__ float Bs[NTILE][17];

    int tid = threadIdx.x, wid = tid >> 5, lane = tid & 31;
    int gid = lane >> 2, tig = lane & 3;
    int wm = (wid & 1) * 64, wn = (wid >> 1) * WN;

    float4 pa[2], pb[BF4];

    auto loadA = [&](int kt) {
        #pragma unroll
        for (int i = 0; i < 2; i++) {
            int slot = tid + i * 256;
            int r = slot >> 2, k4 = (slot & 3) << 2;
            pa[i] = *(const float4*)(A + (size_t)(m0 + r) * lda + kt + k4);
        }
    };
    auto loadB = [&](int kt) {
        #pragma unroll
        for (int i = 0; i < BF4; i++) {
            int slot = tid + i * 256;
            if (!BTRANS) {
                int r = slot >> 2, k4 = (slot & 3) << 2;
                pb[i] = *(const float4*)(B + (size_t)(n0 + r) * ldb + kt + k4);
            } else {
                int kk = slot / (NTILE / 4), n4 = (slot % (NTILE / 4)) * 4;
                pb[i] = *(const float4*)(B + (size_t)(kt + kk) * ldb + n0 + n4);
            }
        }
    };

    loadA(0); loadB(0);
    for (int kt = 0; kt < K; kt += 16) {
        __syncthreads();
        #pragma unroll
        for (int i = 0; i < 2; i++) {
            int slot = tid + i * 256;
            int r = slot >> 2, k4 = (slot & 3) << 2;
            As[r][k4 + 0] = cvt_tf32(pa[i].x);
            As[r][k4 + 1] = cvt_tf32(pa[i].y);
            As[r][k4 + 2] = cvt_tf32(pa[i].z);
            As[r][k4 + 3] = cvt_tf32(pa[i].w);
        }
        #pragma unroll
        for (int i = 0; i < BF4; i++) {
            int slot = tid + i * 256;
            if (!BTRANS) {
                int r = slot >> 2, k4 = (slot & 3) << 2;
                Bs[r][k4 + 0] = cvt_tf32(pb[i].x);
                Bs[r][k4 + 1] = cvt_tf32(pb[i].y);
                Bs[r][k4 + 2] = cvt_tf32(pb[i].z);
                Bs[r][k4 + 3] = cvt_tf32(pb[i].w);
            } else {
                int kk = slot / (NTILE / 4), n4 = (slot % (NTILE / 4)) * 4;
                Bs[n4 + 0][kk] = cvt_tf32(pb[i].x);
                Bs[n4 + 1][kk] = cvt_tf32(pb[i].y);
                Bs[n4 + 2][kk] = cvt_tf32(pb[i].z);
                Bs[n4 + 3][kk] = cvt_tf32(pb[i].w);
            }
        }
        __syncthreads();
        if (kt + 16 < K) { loadA(kt + 16); loadB(kt + 16); }
        #pragma unroll
        for (int kk = 0; kk < 16; kk += 8) {
            uint32_t af[4][4];
            #pragma unroll
            for (int mt = 0; mt < 4; mt++) {
                af[mt][0] = __float_as_uint(As[wm + mt * 16 + gid    ][kk + tig]);
                af[mt][1] = __float_as_uint(As[wm + mt * 16 + gid + 8][kk + tig]);
                af[mt][2] = __float_as_uint(As[wm + mt * 16 + gid    ][kk + tig + 4]);
                af[mt][3] = __float_as_uint(As[wm + mt * 16 + gid + 8][kk + tig + 4]);
            }
            #pragma unroll
            for (int nt = 0; nt < NTN; nt++) {
                uint32_t b0 = __float_as_uint(Bs[wn + nt * 8 + gid][kk + tig]);
                uint32_t b1 = __float_as_uint(Bs[wn + nt * 8 + gid][kk + tig + 4]);
                #pragma unroll
                for (int mt = 0; mt < 4; mt++)
                    mma_tf32(acc[mt][nt], af[mt], b0, b1);
            }
        }
    }
    __syncthreads();
}

#define EPI_SETUP() \
    int tid = threadIdx.x, wid = tid >> 5, lane = tid & 31; \
    int gid = lane >> 2, tig = lane & 3; \
    int wm = (wid & 1) * 64; (void)wm; \
    int wn = (wid >> 1) * WN; (void)wn; (void)tid;

// ---------------- kernel 1: QKV projection (reads x [S,B,E] directly) ----------------
__global__ void k_qkv(const float* __restrict__ x,
                      const float* __restrict__ qkv_w, const float* __restrict__ qkv_b) {
    constexpr int WN = 32;
    int m0 = blockIdx.y * 128, n0 = blockIdx.x * 128;
    int bb = m0 >> 11;
    float acc[4][4][4] = {};
    gemm_mma<128, false>(x + (size_t)bb * EE, BB * EE, qkv_w, EE,
                         m0 & (SS - 1), n0, EE, acc);
    EPI_SETUP();
    int which = n0 >> 10;
    float* dst = (which == 0) ? g_Q : (which == 1) ? g_K : g_V;
    #pragma unroll
    for (int mt = 0; mt < 4; mt++) {
        #pragma unroll
        for (int nt = 0; nt < 4; nt++) {
            int col = n0 + wn + nt * 8 + 2 * tig;
            int inner = col & 1023, h = inner >> 6, dd = inner & 63;
            float b0 = qkv_b[col], b1 = qkv_b[col + 1];
            #pragma unroll
            for (int half = 0; half < 2; half++) {
                int row = m0 + wm + mt * 16 + gid + half * 8;
                int b = row >> 11, s = row & (SS - 1);
                float2 v = make_float2(acc[mt][nt][half * 2] + b0,
                                       acc[mt][nt][half * 2 + 1] + b1);
                *(float2*)&dst[((size_t)(b * HH + h) * SS + s) * DD + dd] = v;
            }
        }
    }
}

// ---------------- kernel 2: scores = QK^T/8 + masks -> g_P ----------------
__global__ void k_scores(const float* __restrict__ attn_mask,
                         const unsigned char* __restrict__ kpm) {
    constexpr int WN = 32;
    int bh = blockIdx.z, b = bh >> 4;
    int m0 = blockIdx.y * 128, n0 = blockIdx.x * 128;
    const float* Aq = g_Q + (size_t)bh * SS * DD;
    const float* Bk = g_K + (size_t)bh * SS * DD;
    float acc[4][4][4] = {};
    gemm_mma<128, false>(Aq, DD, Bk, DD, m0, n0, DD, acc);
    EPI_SETUP();
    float* pbase = g_P + (size_t)bh * SS * SS;
    #pragma unroll
    for (int mt = 0; mt < 4; mt++) {
        #pragma unroll
        for (int nt = 0; nt < 4; nt++) {
            int k = n0 + wn + nt * 8 + 2 * tig;
            float p0 = kpm[b * SS + k]     ? -1e30f : 0.0f;
            float p1 = kpm[b * SS + k + 1] ? -1e30f : 0.0f;
            #pragma unroll
            for (int half = 0; half < 2; half++) {
                int q = m0 + wm + mt * 16 + gid + half * 8;
                const float* am = attn_mask + (size_t)q * SS + k;
                float2 v = make_float2(acc[mt][nt][half * 2]     * 0.125f + am[0] + p0,
                                       acc[mt][nt][half * 2 + 1] * 0.125f + am[1] + p1);
                *(float2*)&pbase[(size_t)q * SS + k] = v;
            }
        }
    }
}

// ---------------- kernel 3: streaming softmax (in place) + attn_mean ----------------
__global__ void k_softmax(float* __restrict__ out_am) {
    int bq = blockIdx.x;
    int b = bq >> 11, q = bq & (SS - 1);
    int tid = threadIdx.x, wid = tid >> 5, lane = tid & 31;
    __shared__ float red[8];
    __shared__ float bc;
    float accv[8] = {};
    float* pbase = g_P + ((size_t)(b * HH) * SS + q) * SS;
    const size_t hstr = (size_t)SS * SS;
    const int c0 = tid * 8;

    for (int h = 0; h < HH; h++) {
        float* gr = pbase + h * hstr;
        float4 v0 = *(float4*)(gr + c0);
        float4 v1 = *(float4*)(gr + c0 + 4);
        float v[8] = {v0.x, v0.y, v0.z, v0.w, v1.x, v1.y, v1.z, v1.w};

        float mx = v[0];
        #pragma unroll
        for (int j = 1; j < 8; j++) mx = fmaxf(mx, v[j]);
        #pragma unroll
        for (int st = 16; st > 0; st >>= 1)
            mx = fmaxf(mx, __shfl_xor_sync(0xFFFFFFFF, mx, st));
        if (lane == 0) red[wid] = mx;
        __syncthreads();
        if (tid == 0) {
            float m = red[0];
            #pragma unroll
            for (int i = 1; i < 8; i++) m = fmaxf(m, red[i]);
            bc = m;
        }
        __syncthreads();
        mx = bc;

        float sum = 0.f;
        #pragma unroll
        for (int j = 0; j < 8; j++) { v[j] = __expf(v[j] - mx); sum += v[j]; }
        #pragma unroll
        for (int st = 16; st > 0; st >>= 1)
            sum += __shfl_xor_sync(0xFFFFFFFF, sum, st);
        __syncthreads();
        if (lane == 0) red[wid] = sum;
        __syncthreads();
        if (tid == 0) {
            float s = 0.f;
            #pragma unroll
            for (int i = 0; i < 8; i++) s += red[i];
            bc = s;
        }
        __syncthreads();
        float inv = 1.0f / bc;

        #pragma unroll
        for (int j = 0; j < 8; j++) { v[j] *= inv; accv[j] += v[j]; }
        *(float4*)(gr + c0)     = make_float4(v[0], v[1], v[2], v[3]);
        *(float4*)(gr + c0 + 4) = make_float4(v[4], v[5], v[6], v[7]);
        __syncthreads();
    }

    float* am = out_am + (size_t)bq * SS;
    *(float4*)(am + c0)     = make_float4(accv[0] * (1.0f / HH), accv[1] * (1.0f / HH),
                                          accv[2] * (1.0f / HH), accv[3] * (1.0f / HH));
    *(float4*)(am + c0 + 4) = make_float4(accv[4] * (1.0f / HH), accv[5] * (1.0f / HH),
                                          accv[6] * (1.0f / HH), accv[7] * (1.0f / HH));
}

// ---------------- kernel 4: O = P @ V ----------------
__global__ void k_pv() {
    constexpr int WN = 16;
    int bh = blockIdx.y, b = bh >> 4, h = bh & 15;
    int m0 = blockIdx.x * 128;
    const float* A  = g_P + (size_t)bh * SS * SS;
    const float* Bv = g_V + (size_t)bh * SS * DD;
    float acc[4][2][4] = {};
    gemm_mma<64, true>(A, SS, Bv, DD, m0, 0, SS, acc);
    EPI_SETUP();
    #pragma unroll
    for (int mt = 0; mt < 4; mt++) {
        #pragma unroll
        for (int nt = 0; nt < 2; nt++) {
            int dd = wn + nt * 8 + 2 * tig;
            #pragma unroll
            for (int half = 0; half < 2; half++) {
                int q = m0 + wm + mt * 16 + gid + half * 8;
                float2 v = make_float2(acc[mt][nt][half * 2], acc[mt][nt][half * 2 + 1]);
                *(float2*)&g_WA[(size_t)(b * SS + q) * EE + h * DD + dd] = v;
            }
        }
    }
}

// ---------------- kernel 5: out = WA @ out_w^T + out_b -> [S,B,E] ----------------
__global__ void k_out(const float* __restrict__ out_w, const float* __restrict__ out_b,
                      float* __restrict__ dout) {
    constexpr int WN = 32;
    int m0 = blockIdx.y * 128, n0 = blockIdx.x * 128;
    float acc[4][4][4] = {};
    gemm_mma<128, false>(g_WA, EE, out_w, EE, m0, n0, EE, acc);
    EPI_SETUP();
    #pragma unroll
    for (int mt = 0; mt < 4; mt++) {
        #pragma unroll
        for (int nt = 0; nt < 4; nt++) {
            int col = n0 + wn + nt * 8 + 2 * tig;
            float b0 = out_b[col], b1 = out_b[col + 1];
            #pragma unroll
            for (int half = 0; half < 2; half++) {
                int row = m0 + wm + mt * 16 + gid + half * 8;
                int b = row >> 11, s = row & (SS - 1);
                float2 v = make_float2(acc[mt][nt][half * 2] + b0,
                                       acc[mt][nt][half * 2 + 1] + b1);
                *(float2*)&dout[((size_t)s * BB + b) * EE + col] = v;
            }
        }
    }
}

// ---------------- launch ----------------
extern "C" void kernel_launch(void* const* d_in, const int* in_sizes, int n_in,
                              void* d_out, int out_size) {
    const float*         x         = (const float*)d_in[0];
    const float*         attn_mask = (const float*)d_in[1];
    const unsigned char* kpm       = (const unsigned char*)d_in[2];
    const float*         qkv_w     = (const float*)d_in[3];
    const float*         qkv_b     = (const float*)d_in[4];
    const float*         out_w     = (const float*)d_in[5];
    const float*         out_b     = (const float*)d_in[6];

    float* out    = (float*)d_out;
    float* out_am = out + (size_t)SS * BB * EE;

    k_qkv<<<dim3(3 * EE / 128, TOK / 128), NT>>>(x, qkv_w, qkv_b);
    k_scores<<<dim3(SS / 128, SS / 128, BH), NT>>>(attn_mask, kpm);
    k_softmax<<<BB * SS, 256>>>(out_am);
    k_pv<<<dim3(SS / 128, BH), NT>>>();
    k_out<<<dim3(EE / 128, TOK / 128), NT>>>(out_w, out_b, out);
}

// round 6
// speedup vs baseline: 2.4968x; 1.3301x over previous
#include <cuda_runtime.h>
#include <cstdint>

#define SS   2048
#define BB   2
#define EE   1024
#define HH   16
#define DD   64
#define BH   (BB*HH)
#define TOK  (BB*SS)
#define NT   256
#define PAD  20          // smem row pitch in floats (80B: 16B-aligned, conflict-free)
#define STG  3           // cp.async pipeline stages

// ---------------- scratch ----------------
__device__ float g_Q[BH * SS * DD];              // [B*H, S, d]
__device__ float g_K[BH * SS * DD];
__device__ float g_Vt[BH * DD * SS];             // V transposed [B*H, d, S]
__device__ float g_P[(size_t)BH * SS * SS];      // attn scores/probs [B*H, S, S]
__device__ float g_WA[TOK * EE];                 // attn out token-major

// ---------------- mma helpers ----------------
__device__ __forceinline__ uint32_t cvt_tf32_u(float f) {
    uint32_t u;
    asm("cvt.rna.tf32.f32 %0, %1;" : "=r"(u) : "f"(f));
    return u;
}

__device__ __forceinline__ void mma_tf32(float c[4], const uint32_t a[4],
                                         uint32_t b0, uint32_t b1) {
    asm volatile("mma.sync.aligned.m16n8k8.row.col.f32.tf32.tf32.f32 "
                 "{%0,%1,%2,%3}, {%4,%5,%6,%7}, {%8,%9}, {%0,%1,%2,%3};"
                 : "+f"(c[0]), "+f"(c[1]), "+f"(c[2]), "+f"(c[3])
                 : "r"(a[0]), "r"(a[1]), "r"(a[2]), "r"(a[3]), "r"(b0), "r"(b1));
}

// ---------------- GEMM core (cp.async 3-stage) ----------------
// C[128 x NTILE] tile at (m0,n0) of A[M,K] @ B[N,K]^T; both row-major; K % 16 == 0.
// 256 threads: 8 warps as 2(m) x 4(n); warp tile 64 x (NTILE/4).
template<int NTILE>
__device__ __forceinline__ void gemm_mma(const float* __restrict__ A, int lda,
                                         const float* __restrict__ B, int ldb,
                                         int m0, int n0, int K,
                                         float acc[4][NTILE/32][4]) {
    constexpr int WN  = NTILE / 4;
    constexpr int NTN = WN / 8;
    extern __shared__ float smb[];
    float* As = smb;                               // [STG][128][PAD]
    float* Bs = smb + STG * 128 * PAD;             // [STG][NTILE][PAD]

    int tid = threadIdx.x, wid = tid >> 5, lane = tid & 31;
    int gid = lane >> 2, tig = lane & 3;
    int wm = (wid & 1) * 64, wn = (wid >> 1) * WN;
    int nIter = K >> 4;

    auto issue = [&](int it) {
        if (it < nIter) {
            int kt = it << 4;
            int buf = it % STG;
            #pragma unroll
            for (int j = 0; j < 2; j++) {
                int slot = tid + j * 256;
                int r = slot >> 2, c4 = (slot & 3) << 2;
                uint32_t dst = (uint32_t)__cvta_generic_to_shared(
                    &As[(buf * 128 + r) * PAD + c4]);
                const float* src = A + (size_t)(m0 + r) * lda + kt + c4;
                asm volatile("cp.async.cg.shared.global [%0], [%1], 16;"
                             :: "r"(dst), "l"(src));
            }
            #pragma unroll
            for (int j = 0; j < NTILE / 64; j++) {
                int slot = tid + j * 256;
                int r = slot >> 2, c4 = (slot & 3) << 2;
                uint32_t dst = (uint32_t)__cvta_generic_to_shared(
                    &Bs[(buf * NTILE + r) * PAD + c4]);
                const float* src = B + (size_t)(n0 + r) * ldb + kt + c4;
                asm volatile("cp.async.cg.shared.global [%0], [%1], 16;"
                             :: "r"(dst), "l"(src));
            }
        }
        asm volatile("cp.async.commit_group;" ::: "memory");
    };

    issue(0); issue(1);
    for (int it = 0; it < nIter; it++) {
        asm volatile("cp.async.wait_group 1;" ::: "memory");
        __syncthreads();
        issue(it + 2);
        const float* Ab = As + (it % STG) * 128 * PAD;
        const float* Bb = Bs + (it % STG) * NTILE * PAD;
        #pragma unroll
        for (int kk = 0; kk < 16; kk += 8) {
            uint32_t af[4][4];
            #pragma unroll
            for (int mt = 0; mt < 4; mt++) {
                af[mt][0] = cvt_tf32_u(Ab[(wm + mt * 16 + gid    ) * PAD + kk + tig]);
                af[mt][1] = cvt_tf32_u(Ab[(wm + mt * 16 + gid + 8) * PAD + kk + tig]);
                af[mt][2] = cvt_tf32_u(Ab[(wm + mt * 16 + gid    ) * PAD + kk + tig + 4]);
                af[mt][3] = cvt_tf32_u(Ab[(wm + mt * 16 + gid + 8) * PAD + kk + tig + 4]);
            }
            #pragma unroll
            for (int nt = 0; nt < NTN; nt++) {
                uint32_t b0 = cvt_tf32_u(Bb[(wn + nt * 8 + gid) * PAD + kk + tig]);
                uint32_t b1 = cvt_tf32_u(Bb[(wn + nt * 8 + gid) * PAD + kk + tig + 4]);
                #pragma unroll
                for (int mt = 0; mt < 4; mt++)
                    mma_tf32(acc[mt][nt], af[mt], b0, b1);
            }
        }
        __syncthreads();
    }
}

#define EPI_SETUP() \
    int tid = threadIdx.x, wid = tid >> 5, lane = tid & 31; \
    int gid = lane >> 2, tig = lane & 3; \
    int wm = (wid & 1) * 64; (void)wm; \
    int wn = (wid >> 1) * WN; (void)wn; (void)tid;

// ---------------- kernel 1: QKV projection (reads x [S,B,E] directly) ----------------
__global__ void k_qkv(const float* __restrict__ x,
                      const float* __restrict__ qkv_w, const float* __restrict__ qkv_b) {
    constexpr int WN = 32;
    int m0 = blockIdx.y * 128, n0 = blockIdx.x * 128;
    int bb = m0 >> 11;
    float acc[4][4][4] = {};
    gemm_mma<128>(x + (size_t)bb * EE, BB * EE, qkv_w, EE, m0 & (SS - 1), n0, EE, acc);
    EPI_SETUP();
    int which = n0 >> 10;
    #pragma unroll
    for (int mt = 0; mt < 4; mt++) {
        #pragma unroll
        for (int nt = 0; nt < 4; nt++) {
            int col = n0 + wn + nt * 8 + 2 * tig;
            int inner = col & 1023, h = inner >> 6, dd = inner & 63;
            float b0 = qkv_b[col], b1 = qkv_b[col + 1];
            #pragma unroll
            for (int half = 0; half < 2; half++) {
                int row = m0 + wm + mt * 16 + gid + half * 8;
                int b = row >> 11, s = row & (SS - 1);
                float v0 = acc[mt][nt][half * 2] + b0;
                float v1 = acc[mt][nt][half * 2 + 1] + b1;
                if (which == 2) {
                    size_t base = (size_t)(b * HH + h) * DD;
                    g_Vt[(base + dd)     * SS + s] = v0;
                    g_Vt[(base + dd + 1) * SS + s] = v1;
                } else {
                    float* dst = which ? g_K : g_Q;
                    *(float2*)&dst[((size_t)(b * HH + h) * SS + s) * DD + dd] =
                        make_float2(v0, v1);
                }
            }
        }
    }
}

// ---------------- kernel 2: scores = QK^T/8 + masks -> g_P ----------------
__global__ void k_scores(const float* __restrict__ attn_mask,
                         const unsigned char* __restrict__ kpm) {
    constexpr int WN = 32;
    int bh = blockIdx.z, b = bh >> 4;
    int m0 = blockIdx.y * 128, n0 = blockIdx.x * 128;
    const float* Aq = g_Q + (size_t)bh * SS * DD;
    const float* Bk = g_K + (size_t)bh * SS * DD;
    float acc[4][4][4] = {};
    gemm_mma<128>(Aq, DD, Bk, DD, m0, n0, DD, acc);
    EPI_SETUP();
    float* pbase = g_P + (size_t)bh * SS * SS;
    #pragma unroll
    for (int mt = 0; mt < 4; mt++) {
        #pragma unroll
        for (int nt = 0; nt < 4; nt++) {
            int k = n0 + wn + nt * 8 + 2 * tig;
            float p0 = kpm[b * SS + k]     ? -1e30f : 0.0f;
            float p1 = kpm[b * SS + k + 1] ? -1e30f : 0.0f;
            #pragma unroll
            for (int half = 0; half < 2; half++) {
                int q = m0 + wm + mt * 16 + gid + half * 8;
                const float* am = attn_mask + (size_t)q * SS + k;
                float2 v = make_float2(acc[mt][nt][half * 2]     * 0.125f + am[0] + p0,
                                       acc[mt][nt][half * 2 + 1] * 0.125f + am[1] + p1);
                *(float2*)&pbase[(size_t)q * SS + k] = v;
            }
        }
    }
}

// ---------------- kernel 3: streaming softmax (in place) + attn_mean ----------------
__global__ void k_softmax(float* __restrict__ out_am) {
    int bq = blockIdx.x;
    int b = bq >> 11, q = bq & (SS - 1);
    int tid = threadIdx.x, wid = tid >> 5, lane = tid & 31;
    __shared__ float red[8];
    __shared__ float bc;
    float accv[8] = {};
    float* pbase = g_P + ((size_t)(b * HH) * SS + q) * SS;
    const size_t hstr = (size_t)SS * SS;
    const int c0 = tid * 8;

    for (int h = 0; h < HH; h++) {
        float* gr = pbase + h * hstr;
        float4 v0 = *(float4*)(gr + c0);
        float4 v1 = *(float4*)(gr + c0 + 4);
        float v[8] = {v0.x, v0.y, v0.z, v0.w, v1.x, v1.y, v1.z, v1.w};

        float mx = v[0];
        #pragma unroll
        for (int j = 1; j < 8; j++) mx = fmaxf(mx, v[j]);
        #pragma unroll
        for (int st = 16; st > 0; st >>= 1)
            mx = fmaxf(mx, __shfl_xor_sync(0xFFFFFFFF, mx, st));
        if (lane == 0) red[wid] = mx;
        __syncthreads();
        if (tid == 0) {
            float m = red[0];
            #pragma unroll
            for (int i = 1; i < 8; i++) m = fmaxf(m, red[i]);
            bc = m;
        }
        __syncthreads();
        mx = bc;

        float sum = 0.f;
        #pragma unroll
        for (int j = 0; j < 8; j++) { v[j] = __expf(v[j] - mx); sum += v[j]; }
        #pragma unroll
        for (int st = 16; st > 0; st >>= 1)
            sum += __shfl_xor_sync(0xFFFFFFFF, sum, st);
        __syncthreads();
        if (lane == 0) red[wid] = sum;
        __syncthreads();
        if (tid == 0) {
            float s = 0.f;
            #pragma unroll
            for (int i = 0; i < 8; i++) s += red[i];
            bc = s;
        }
        __syncthreads();
        float inv = 1.0f / bc;

        #pragma unroll
        for (int j = 0; j < 8; j++) { v[j] *= inv; accv[j] += v[j]; }
        *(float4*)(gr + c0)     = make_float4(v[0], v[1], v[2], v[3]);
        *(float4*)(gr + c0 + 4) = make_float4(v[4], v[5], v[6], v[7]);
        __syncthreads();
    }

    float* am = out_am + (size_t)bq * SS;
    *(float4*)(am + c0)     = make_float4(accv[0] * (1.0f / HH), accv[1] * (1.0f / HH),
                                          accv[2] * (1.0f / HH), accv[3] * (1.0f / HH));
    *(float4*)(am + c0 + 4) = make_float4(accv[4] * (1.0f / HH), accv[5] * (1.0f / HH),
                                          accv[6] * (1.0f / HH), accv[7] * (1.0f / HH));
}

// ---------------- kernel 4: O = P @ Vt^T ----------------
__global__ void k_pv() {
    constexpr int WN = 16;
    int bh = blockIdx.y, b = bh >> 4, h = bh & 15;
    int m0 = blockIdx.x * 128;
    const float* A  = g_P  + (size_t)bh * SS * SS;
    const float* Bv = g_Vt + (size_t)bh * DD * SS;   // [d][s] row-major = B[N][K]
    float acc[4][2][4] = {};
    gemm_mma<64>(A, SS, Bv, SS, m0, 0, SS, acc);
    EPI_SETUP();
    #pragma unroll
    for (int mt = 0; mt < 4; mt++) {
        #pragma unroll
        for (int nt = 0; nt < 2; nt++) {
            int dd = wn + nt * 8 + 2 * tig;
            #pragma unroll
            for (int half = 0; half < 2; half++) {
                int q = m0 + wm + mt * 16 + gid + half * 8;
                float2 v = make_float2(acc[mt][nt][half * 2], acc[mt][nt][half * 2 + 1]);
                *(float2*)&g_WA[(size_t)(b * SS + q) * EE + h * DD + dd] = v;
            }
        }
    }
}

// ---------------- kernel 5: out = WA @ out_w^T + out_b -> [S,B,E] ----------------
__global__ void k_out(const float* __restrict__ out_w, const float* __restrict__ out_b,
                      float* __restrict__ dout) {
    constexpr int WN = 32;
    int m0 = blockIdx.y * 128, n0 = blockIdx.x * 128;
    float acc[4][4][4] = {};
    gemm_mma<128>(g_WA, EE, out_w, EE, m0, n0, EE, acc);
    EPI_SETUP();
    #pragma unroll
    for (int mt = 0; mt < 4; mt++) {
        #pragma unroll
        for (int nt = 0; nt < 4; nt++) {
            int col = n0 + wn + nt * 8 + 2 * tig;
            float b0 = out_b[col], b1 = out_b[col + 1];
            #pragma unroll
            for (int half = 0; half < 2; half++) {
                int row = m0 + wm + mt * 16 + gid + half * 8;
                int b = row >> 11, s = row & (SS - 1);
                float2 v = make_float2(acc[mt][nt][half * 2] + b0,
                                       acc[mt][nt][half * 2 + 1] + b1);
                *(float2*)&dout[((size_t)s * BB + b) * EE + col] = v;
            }
        }
    }
}

// ---------------- launch ----------------
extern "C" void kernel_launch(void* const* d_in, const int* in_sizes, int n_in,
                              void* d_out, int out_size) {
    const float*         x         = (const float*)d_in[0];
    const float*         attn_mask = (const float*)d_in[1];
    const unsigned char* kpm       = (const unsigned char*)d_in[2];
    const float*         qkv_w     = (const float*)d_in[3];
    const float*         qkv_b     = (const float*)d_in[4];
    const float*         out_w     = (const float*)d_in[5];
    const float*         out_b     = (const float*)d_in[6];

    float* out    = (float*)d_out;
    float* out_am = out + (size_t)SS * BB * EE;

    const int smem128 = STG * (128 + 128) * PAD * 4;   // 61440
    const int smem64  = STG * (128 + 64)  * PAD * 4;   // 46080
    cudaFuncSetAttribute(k_qkv,    cudaFuncAttributeMaxDynamicSharedMemorySize, smem128);
    cudaFuncSetAttribute(k_scores, cudaFuncAttributeMaxDynamicSharedMemorySize, smem128);
    cudaFuncSetAttribute(k_out,    cudaFuncAttributeMaxDynamicSharedMemorySize, smem128);
    cudaFuncSetAttribute(k_pv,     cudaFuncAttributeMaxDynamicSharedMemorySize, smem64);

    k_qkv<<<dim3(3 * EE / 128, TOK / 128), NT, smem128>>>(x, qkv_w, qkv_b);
    k_scores<<<dim3(SS / 128, SS / 128, BH), NT, smem128>>>(attn_mask, kpm);
    k_softmax<<<BB * SS, 256>>>(out_am);
    k_pv<<<dim3(SS / 128, BH), NT, smem64>>>();
    k_out<<<dim3(EE / 128, TOK / 128), NT, smem128>>>(out_w, out_b, out);
}

// round 7
// speedup vs baseline: 2.5132x; 1.0066x over previous
#include <cuda_runtime.h>
#include <cstdint>

#define SS   2048
#define BB   2
#define EE   1024
#define HH   16
#define DD   64
#define BH   (BB*HH)
#define TOK  (BB*SS)
#define NT   256
#define PAD  20          // smem row pitch in floats (80B: 16B-aligned, conflict-free)
#define STG  3           // cp.async pipeline stages

// ---------------- scratch ----------------
__device__ float g_Q[BH * SS * DD];              // [B*H, S, d]
__device__ float g_K[BH * SS * DD];
__device__ float g_Vt[BH * DD * SS];             // V transposed [B*H, d, S]
__device__ float g_P[(size_t)BH * SS * SS];      // attn scores/probs [B*H, S, S]
__device__ float g_WA[TOK * EE];                 // attn out token-major

// ---------------- mma helpers ----------------
__device__ __forceinline__ uint32_t cvt_tf32_u(float f) {
    uint32_t u;
    asm("cvt.rna.tf32.f32 %0, %1;" : "=r"(u) : "f"(f));
    return u;
}

__device__ __forceinline__ void mma_tf32(float c[4], const uint32_t a[4],
                                         uint32_t b0, uint32_t b1) {
    asm volatile("mma.sync.aligned.m16n8k8.row.col.f32.tf32.tf32.f32 "
                 "{%0,%1,%2,%3}, {%4,%5,%6,%7}, {%8,%9}, {%0,%1,%2,%3};"
                 : "+f"(c[0]), "+f"(c[1]), "+f"(c[2]), "+f"(c[3])
                 : "r"(a[0]), "r"(a[1]), "r"(a[2]), "r"(a[3]), "r"(b0), "r"(b1));
}

// ---------------- GEMM core (cp.async 3-stage) ----------------
// C[128 x NTILE] tile at (m0,n0) of A[M,K] @ B[N,K]^T; both row-major; K % 16 == 0.
// 256 threads: 8 warps as 2(m) x 4(n); warp tile 64 x (NTILE/4).
template<int NTILE>
__device__ __forceinline__ void gemm_mma(const float* __restrict__ A, int lda,
                                         const float* __restrict__ B, int ldb,
                                         int m0, int n0, int K,
                                         float acc[4][NTILE/32][4]) {
    constexpr int WN  = NTILE / 4;
    constexpr int NTN = WN / 8;
    extern __shared__ float smb[];
    float* As = smb;                               // [STG][128][PAD]
    float* Bs = smb + STG * 128 * PAD;             // [STG][NTILE][PAD]

    int tid = threadIdx.x, wid = tid >> 5, lane = tid & 31;
    int gid = lane >> 2, tig = lane & 3;
    int wm = (wid & 1) * 64, wn = (wid >> 1) * WN;
    int nIter = K >> 4;

    auto issue = [&](int it) {
        if (it < nIter) {
            int kt = it << 4;
            int buf = it % STG;
            #pragma unroll
            for (int j = 0; j < 2; j++) {
                int slot = tid + j * 256;
                int r = slot >> 2, c4 = (slot & 3) << 2;
                uint32_t dst = (uint32_t)__cvta_generic_to_shared(
                    &As[(buf * 128 + r) * PAD + c4]);
                const float* src = A + (size_t)(m0 + r) * lda + kt + c4;
                asm volatile("cp.async.cg.shared.global [%0], [%1], 16;"
                             :: "r"(dst), "l"(src));
            }
            #pragma unroll
            for (int j = 0; j < NTILE / 64; j++) {
                int slot = tid + j * 256;
                int r = slot >> 2, c4 = (slot & 3) << 2;
                uint32_t dst = (uint32_t)__cvta_generic_to_shared(
                    &Bs[(buf * NTILE + r) * PAD + c4]);
                const float* src = B + (size_t)(n0 + r) * ldb + kt + c4;
                asm volatile("cp.async.cg.shared.global [%0], [%1], 16;"
                             :: "r"(dst), "l"(src));
            }
        }
        asm volatile("cp.async.commit_group;" ::: "memory");
    };

    issue(0); issue(1);
    for (int it = 0; it < nIter; it++) {
        asm volatile("cp.async.wait_group 1;" ::: "memory");
        __syncthreads();
        issue(it + 2);
        const float* Ab = As + (it % STG) * 128 * PAD;
        const float* Bb = Bs + (it % STG) * NTILE * PAD;
        #pragma unroll
        for (int kk = 0; kk < 16; kk += 8) {
            uint32_t af[4][4];
            #pragma unroll
            for (int mt = 0; mt < 4; mt++) {
                af[mt][0] = cvt_tf32_u(Ab[(wm + mt * 16 + gid    ) * PAD + kk + tig]);
                af[mt][1] = cvt_tf32_u(Ab[(wm + mt * 16 + gid + 8) * PAD + kk + tig]);
                af[mt][2] = cvt_tf32_u(Ab[(wm + mt * 16 + gid    ) * PAD + kk + tig + 4]);
                af[mt][3] = cvt_tf32_u(Ab[(wm + mt * 16 + gid + 8) * PAD + kk + tig + 4]);
            }
            #pragma unroll
            for (int nt = 0; nt < NTN; nt++) {
                uint32_t b0 = cvt_tf32_u(Bb[(wn + nt * 8 + gid) * PAD + kk + tig]);
                uint32_t b1 = cvt_tf32_u(Bb[(wn + nt * 8 + gid) * PAD + kk + tig + 4]);
                #pragma unroll
                for (int mt = 0; mt < 4; mt++)
                    mma_tf32(acc[mt][nt], af[mt], b0, b1);
            }
        }
        __syncthreads();
    }
}

#define EPI_SETUP() \
    int tid = threadIdx.x, wid = tid >> 5, lane = tid & 31; \
    int gid = lane >> 2, tig = lane & 3; \
    int wm = (wid & 1) * 64; (void)wm; \
    int wn = (wid >> 1) * WN; (void)wn; (void)tid;

// ---------------- kernel 1: QKV projection (reads x [S,B,E] directly) ----------------
__global__ void k_qkv(const float* __restrict__ x,
                      const float* __restrict__ qkv_w, const float* __restrict__ qkv_b) {
    constexpr int WN = 32;
    int m0 = blockIdx.y * 128, n0 = blockIdx.x * 128;
    int bb = m0 >> 11;
    float acc[4][4][4] = {};
    gemm_mma<128>(x + (size_t)bb * EE, BB * EE, qkv_w, EE, m0 & (SS - 1), n0, EE, acc);
    EPI_SETUP();
    int which = n0 >> 10;
    #pragma unroll
    for (int mt = 0; mt < 4; mt++) {
        #pragma unroll
        for (int nt = 0; nt < 4; nt++) {
            int col = n0 + wn + nt * 8 + 2 * tig;
            int inner = col & 1023, h = inner >> 6, dd = inner & 63;
            float b0 = qkv_b[col], b1 = qkv_b[col + 1];
            #pragma unroll
            for (int half = 0; half < 2; half++) {
                int row = m0 + wm + mt * 16 + gid + half * 8;
                int b = row >> 11, s = row & (SS - 1);
                float v0 = acc[mt][nt][half * 2] + b0;
                float v1 = acc[mt][nt][half * 2 + 1] + b1;
                if (which == 2) {
                    size_t base = (size_t)(b * HH + h) * DD;
                    g_Vt[(base + dd)     * SS + s] = v0;
                    g_Vt[(base + dd + 1) * SS + s] = v1;
                } else {
                    float* dst = which ? g_K : g_Q;
                    *(float2*)&dst[((size_t)(b * HH + h) * SS + s) * DD + dd] =
                        make_float2(v0, v1);
                }
            }
        }
    }
}

// ---------------- kernel 2: scores = QK^T/8 + masks -> g_P ----------------
__global__ void k_scores(const float* __restrict__ attn_mask,
                         const unsigned char* __restrict__ kpm) {
    constexpr int WN = 32;
    int bh = blockIdx.z, b = bh >> 4;
    int m0 = blockIdx.y * 128, n0 = blockIdx.x * 128;
    const float* Aq = g_Q + (size_t)bh * SS * DD;
    const float* Bk = g_K + (size_t)bh * SS * DD;
    float acc[4][4][4] = {};
    gemm_mma<128>(Aq, DD, Bk, DD, m0, n0, DD, acc);
    EPI_SETUP();
    float* pbase = g_P + (size_t)bh * SS * SS;
    #pragma unroll
    for (int mt = 0; mt < 4; mt++) {
        #pragma unroll
        for (int nt = 0; nt < 4; nt++) {
            int k = n0 + wn + nt * 8 + 2 * tig;
            float p0 = kpm[b * SS + k]     ? -1e30f : 0.0f;
            float p1 = kpm[b * SS + k + 1] ? -1e30f : 0.0f;
            #pragma unroll
            for (int half = 0; half < 2; half++) {
                int q = m0 + wm + mt * 16 + gid + half * 8;
                const float* am = attn_mask + (size_t)q * SS + k;
                float2 v = make_float2(acc[mt][nt][half * 2]     * 0.125f + am[0] + p0,
                                       acc[mt][nt][half * 2 + 1] * 0.125f + am[1] + p1);
                *(float2*)&pbase[(size_t)q * SS + k] = v;
            }
        }
    }
}

// ---------------- kernel 3: streaming softmax (in place) + attn_mean ----------------
__global__ void k_softmax(float* __restrict__ out_am) {
    int bq = blockIdx.x;
    int b = bq >> 11, q = bq & (SS - 1);
    int tid = threadIdx.x, wid = tid >> 5, lane = tid & 31;
    __shared__ float red[8];
    __shared__ float bc;
    float accv[8] = {};
    float* pbase = g_P + ((size_t)(b * HH) * SS + q) * SS;
    const size_t hstr = (size_t)SS * SS;
    const int c0 = tid * 8;

    for (int h = 0; h < HH; h++) {
        float* gr = pbase + h * hstr;
        float4 v0 = *(float4*)(gr + c0);
        float4 v1 = *(float4*)(gr + c0 + 4);
        float v[8] = {v0.x, v0.y, v0.z, v0.w, v1.x, v1.y, v1.z, v1.w};

        float mx = v[0];
        #pragma unroll
        for (int j = 1; j < 8; j++) mx = fmaxf(mx, v[j]);
        #pragma unroll
        for (int st = 16; st > 0; st >>= 1)
            mx = fmaxf(mx, __shfl_xor_sync(0xFFFFFFFF, mx, st));
        if (lane == 0) red[wid] = mx;
        __syncthreads();
        if (tid == 0) {
            float m = red[0];
            #pragma unroll
            for (int i = 1; i < 8; i++) m = fmaxf(m, red[i]);
            bc = m;
        }
        __syncthreads();
        mx = bc;

        float sum = 0.f;
        #pragma unroll
        for (int j = 0; j < 8; j++) { v[j] = __expf(v[j] - mx); sum += v[j]; }
        #pragma unroll
        for (int st = 16; st > 0; st >>= 1)
            sum += __shfl_xor_sync(0xFFFFFFFF, sum, st);
        __syncthreads();
        if (lane == 0) red[wid] = sum;
        __syncthreads();
        if (tid == 0) {
            float s = 0.f;
            #pragma unroll
            for (int i = 0; i < 8; i++) s += red[i];
            bc = s;
        }
        __syncthreads();
        float inv = 1.0f / bc;

        #pragma unroll
        for (int j = 0; j < 8; j++) { v[j] *= inv; accv[j] += v[j]; }
        *(float4*)(gr + c0)     = make_float4(v[0], v[1], v[2], v[3]);
        *(float4*)(gr + c0 + 4) = make_float4(v[4], v[5], v[6], v[7]);
        __syncthreads();
    }

    float* am = out_am + (size_t)bq * SS;
    *(float4*)(am + c0)     = make_float4(accv[0] * (1.0f / HH), accv[1] * (1.0f / HH),
                                          accv[2] * (1.0f / HH), accv[3] * (1.0f / HH));
    *(float4*)(am + c0 + 4) = make_float4(accv[4] * (1.0f / HH), accv[5] * (1.0f / HH),
                                          accv[6] * (1.0f / HH), accv[7] * (1.0f / HH));
}

// ---------------- kernel 4: O = P @ Vt^T ----------------
__global__ void k_pv() {
    constexpr int WN = 16;
    int bh = blockIdx.y, b = bh >> 4, h = bh & 15;
    int m0 = blockIdx.x * 128;
    const float* A  = g_P  + (size_t)bh * SS * SS;
    const float* Bv = g_Vt + (size_t)bh * DD * SS;   // [d][s] row-major = B[N][K]
    float acc[4][2][4] = {};
    gemm_mma<64>(A, SS, Bv, SS, m0, 0, SS, acc);
    EPI_SETUP();
    #pragma unroll
    for (int mt = 0; mt < 4; mt++) {
        #pragma unroll
        for (int nt = 0; nt < 2; nt++) {
            int dd = wn + nt * 8 + 2 * tig;
            #pragma unroll
            for (int half = 0; half < 2; half++) {
                int q = m0 + wm + mt * 16 + gid + half * 8;
                float2 v = make_float2(acc[mt][nt][half * 2], acc[mt][nt][half * 2 + 1]);
                *(float2*)&g_WA[(size_t)(b * SS + q) * EE + h * DD + dd] = v;
            }
        }
    }
}

// ---------------- kernel 5: out = WA @ out_w^T + out_b -> [S,B,E] ----------------
__global__ void k_out(const float* __restrict__ out_w, const float* __restrict__ out_b,
                      float* __restrict__ dout) {
    constexpr int WN = 32;
    int m0 = blockIdx.y * 128, n0 = blockIdx.x * 128;
    float acc[4][4][4] = {};
    gemm_mma<128>(g_WA, EE, out_w, EE, m0, n0, EE, acc);
    EPI_SETUP();
    #pragma unroll
    for (int mt = 0; mt < 4; mt++) {
        #pragma unroll
        for (int nt = 0; nt < 4; nt++) {
            int col = n0 + wn + nt * 8 + 2 * tig;
            float b0 = out_b[col], b1 = out_b[col + 1];
            #pragma unroll
            for (int half = 0; half < 2; half++) {
                int row = m0 + wm + mt * 16 + gid + half * 8;
                int b = row >> 11, s = row & (SS - 1);
                float2 v = make_float2(acc[mt][nt][half * 2] + b0,
                                       acc[mt][nt][half * 2 + 1] + b1);
                *(float2*)&dout[((size_t)s * BB + b) * EE + col] = v;
            }
        }
    }
}

// ---------------- launch ----------------
extern "C" void kernel_launch(void* const* d_in, const int* in_sizes, int n_in,
                              void* d_out, int out_size) {
    const float*         x         = (const float*)d_in[0];
    const float*         attn_mask = (const float*)d_in[1];
    const unsigned char* kpm       = (const unsigned char*)d_in[2];
    const float*         qkv_w     = (const float*)d_in[3];
    const float*         qkv_b     = (const float*)d_in[4];
    const float*         out_w     = (const float*)d_in[5];
    const float*         out_b     = (const float*)d_in[6];

    float* out    = (float*)d_out;
    float* out_am = out + (size_t)SS * BB * EE;

    const int smem128 = STG * (128 + 128) * PAD * 4;   // 61440
    const int smem64  = STG * (128 + 64)  * PAD * 4;   // 46080
    cudaFuncSetAttribute(k_qkv,    cudaFuncAttributeMaxDynamicSharedMemorySize, smem128);
    cudaFuncSetAttribute(k_scores, cudaFuncAttributeMaxDynamicSharedMemorySize, smem128);
    cudaFuncSetAttribute(k_out,    cudaFuncAttributeMaxDynamicSharedMemorySize, smem128);
    cudaFuncSetAttribute(k_pv,     cudaFuncAttributeMaxDynamicSharedMemorySize, smem64);

    k_qkv<<<dim3(3 * EE / 128, TOK / 128), NT, smem128>>>(x, qkv_w, qkv_b);
    k_scores<<<dim3(SS / 128, SS / 128, BH), NT, smem128>>>(attn_mask, kpm);
    k_softmax<<<BB * SS, 256>>>(out_am);
    k_pv<<<dim3(SS / 128, BH), NT, smem64>>>();
    k_out<<<dim3(EE / 128, TOK / 128), NT, smem128>>>(out_w, out_b, out);
}